// round 16
// baseline (speedup 1.0000x reference)
#include <cuda_runtime.h>
#include <math.h>

#define BS   8
#define HW   1024
#define STEP 20
#define NS   51            // hw // STEP
#define NP   512           // model points
#define NBLK (BS * NS)     // 408 hypotheses
#define NT   512           // 16 warps, 2 m-tiles (32 query rows) each
#define NTILE 64           // n-tiles of 8 GT points
#define SW   536           // tf32 smem row stride (words): 512 + pad
#define SCORING_WEIGHT 0.01f

// smem (words): [r_hi 4*SW][r_lo 4*SW][pn_s NP][red NT]
#define OFF_RLO (4 * SW)
#define SMEM_WORDS (8 * SW + NP + NT)

// Scratch (no allocations allowed)
__device__ float    g_part[NBLK];
__device__ unsigned g_count = 0;   // last-block-done counter; self-resetting

__device__ __forceinline__ unsigned f2tf(float f) {
    unsigned r; asm("cvt.rna.tf32.f32 %0, %1;" : "=r"(r) : "f"(f)); return r;
}

// D = A(tf32 m16k8,row) * B(tf32 k8n8,col) + 0
#define MMA_Z(D0,D1,D2,D3,A0,A1,A2,A3,B0,B1)                                   \
    asm("mma.sync.aligned.m16n8k8.row.col.f32.tf32.tf32.f32 "                  \
        "{%0,%1,%2,%3}, {%4,%5,%6,%7}, {%8,%9}, {%10,%10,%10,%10};"            \
        : "=f"(D0),"=f"(D1),"=f"(D2),"=f"(D3)                                  \
        : "r"(A0),"r"(A1),"r"(A2),"r"(A3), "r"(B0),"r"(B1), "f"(0.0f))

// D = A * B + C  (C separate from D)
#define MMA_C(D0,D1,D2,D3,A0,A1,A2,A3,B0,B1,C0,C1,C2,C3)                       \
    asm("mma.sync.aligned.m16n8k8.row.col.f32.tf32.tf32.f32 "                  \
        "{%0,%1,%2,%3}, {%4,%5,%6,%7}, {%8,%9}, {%10,%11,%12,%13};"            \
        : "=f"(D0),"=f"(D1),"=f"(D2),"=f"(D3)                                  \
        : "r"(A0),"r"(A1),"r"(A2),"r"(A3), "r"(B0),"r"(B1),                    \
          "f"(C0),"f"(C1),"f"(C2),"f"(C3))

// ---------------------------------------------------------------------------
// One block per hypothesis, 16 warps, 2 m-tiles (32 query rows) per warp.
//   A (m16 x k8) = [-2*pred_hi (k0..2) | 1 | -2*pred_lo (k4..6) | 0]
//   e(t) = A*B_hi(t),  d(t) = A*B_lo(t) + e(t)  =  gn - 2 p.g  (split tf32)
// FULL software pipeline, per iteration nt:
//   issue d(nt+1) (uses e(nt+1), one iter old)
//   issue e(nt+2) (init, two iters ahead of its consumer)
//   min on d(nt)  (one full iteration after its producing HMMA)
// -> no consumer within ~50 cycles of its HMMA; tensor pipe can stream.
// ---------------------------------------------------------------------------
__global__ __launch_bounds__(NT, 2) void fused_kernel(
    const float* __restrict__ pred_r,
    const float* __restrict__ pred_t,
    const float* __restrict__ pred_s,
    const float* __restrict__ gt_r,
    const float* __restrict__ gt_t,
    const float* __restrict__ model,
    float* __restrict__ out)
{
    extern __shared__ unsigned dsm[];
    unsigned* r_hi = dsm;                          // 4*SW (A staging, then B)
    unsigned* r_lo = dsm + OFF_RLO;                // 4*SW
    float*    pn_s = (float*)(dsm + 8 * SW);       // NP
    float*    red  = (float*)(dsm + 8 * SW + NP);  // NT
    __shared__ bool s_last;

    int blk = blockIdx.x;
    int b   = blk / NS;
    int pix = (blk % NS) * STEP;
    int tid = threadIdx.x;

    const float* m = model + b * 3 * NP;

    // ---- pose (redundant per thread) ----
    const float* pr = pred_r + b * 4 * HW + pix;
    float q0 = pr[0], q1 = pr[HW], q2 = pr[2 * HW], q3 = pr[3 * HW];
    float inv = rsqrtf(q0 * q0 + q1 * q1 + q2 * q2 + q3 * q3);
    q0 *= inv; q1 *= inv; q2 *= inv; q3 *= inv;

    float R00 = 1.0f - 2.0f * (q2 * q2 + q3 * q3);
    float R01 = 2.0f * (q1 * q2 - q0 * q3);
    float R02 = 2.0f * (q0 * q2 + q1 * q3);
    float R10 = 2.0f * (q1 * q2 + q3 * q0);
    float R11 = 1.0f - 2.0f * (q1 * q1 + q3 * q3);
    float R12 = 2.0f * (q2 * q3 - q0 * q1);
    float R20 = 2.0f * (q1 * q3 - q0 * q2);
    float R21 = 2.0f * (q0 * q1 + q2 * q3);
    float R22 = 1.0f - 2.0f * (q1 * q1 + q2 * q2);

    const float* pt = pred_t + b * 3 * HW + pix;
    float tx = pt[0], ty = pt[HW], tz = pt[2 * HW];

    // ---- phase 1: one model point per thread: pred -> A staging, gt kept ----
    float vx = m[tid], vy = m[NP + tid], vz = m[2 * NP + tid];
    float gv[4];
    {
        float px = fmaf(R00, vx, fmaf(R01, vy, fmaf(R02, vz, tx)));
        float py = fmaf(R10, vx, fmaf(R11, vy, fmaf(R12, vz, ty)));
        float pz = fmaf(R20, vx, fmaf(R21, vy, fmaf(R22, vz, tz)));
        pn_s[tid] = fmaf(px, px, fmaf(py, py, pz * pz));
        float av[3] = { -2.0f * px, -2.0f * py, -2.0f * pz };
#pragma unroll
        for (int c = 0; c < 3; c++) {
            unsigned hi = f2tf(av[c]);
            r_hi[c * SW + tid] = hi;
            r_lo[c * SW + tid] = f2tf(av[c] - __uint_as_float(hi));
        }
        r_hi[3 * SW + tid] = f2tf(1.0f);
        r_lo[3 * SW + tid] = 0u;

        const float* GR = gt_r + b * 9;
        const float* GTt = gt_t + b * 3;
        float gx = fmaf(GR[0], vx, fmaf(GR[1], vy, fmaf(GR[2], vz, GTt[0])));
        float gy = fmaf(GR[3], vx, fmaf(GR[4], vy, fmaf(GR[5], vz, GTt[1])));
        float gz = fmaf(GR[6], vx, fmaf(GR[7], vy, fmaf(GR[8], vz, GTt[2])));
        gv[0] = gx; gv[1] = gy; gv[2] = gz;
        gv[3] = fmaf(gx, gx, fmaf(gy, gy, gz * gz));
    }
    __syncthreads();

    int lane = tid & 31;
    int w    = tid >> 5;        // warp 0..15
    int lq   = lane >> 2;       // 0..7
    int lk   = lane & 3;        // 0..3
    int mbase = w * 32;

    // ---- phase 2: A fragments for 2 m-tiles (register-resident) ----
    unsigned Ah0[2], Ah1[2], Al0[2], Al1[2];
#pragma unroll
    for (int mt = 0; mt < 2; mt++) {
        int r0 = mbase + mt * 16 + lq;
        Ah0[mt] = r_hi[lk * SW + r0];
        Ah1[mt] = r_hi[lk * SW + r0 + 8];
        Al0[mt] = r_lo[lk * SW + r0];
        Al1[mt] = r_lo[lk * SW + r0 + 8];
    }
    __syncthreads();

    // ---- phase 3: GT -> B tf32 staging (overwrite A buffers) ----
#pragma unroll
    for (int c = 0; c < 4; c++) {
        unsigned hi = f2tf(gv[c]);
        r_hi[c * SW + tid] = hi;
        r_lo[c * SW + tid] = f2tf(gv[c] - __uint_as_float(hi));
    }
    __syncthreads();

    float mnA[2], mnB[2];
    mnA[0] = mnA[1] = mnB[0] = mnB[1] = 3.0e38f;

    const unsigned* bp = r_hi + lk * SW + lq;   // B_lo at +OFF_RLO
    unsigned bz = 0u;

    // e_s[t&1] = e(t), d_s[t&1] = d(t); double-buffered via unroll renaming
    float e_s[2][2][4], d_s[2][2][4];

    // ---- pipeline prologue: e(0), d(0), e(1) ----
    {
        unsigned bh0 = bp[0];
        unsigned bl0 = bp[OFF_RLO];
#pragma unroll
        for (int mt = 0; mt < 2; mt++)
            MMA_Z(e_s[0][mt][0], e_s[0][mt][1], e_s[0][mt][2], e_s[0][mt][3],
                  Ah0[mt], Ah1[mt], Al0[mt], Al1[mt], bh0, bh0);
#pragma unroll
        for (int mt = 0; mt < 2; mt++)
            MMA_C(d_s[0][mt][0], d_s[0][mt][1], d_s[0][mt][2], d_s[0][mt][3],
                  Ah0[mt], Ah1[mt], Al0[mt], Al1[mt], bl0, bz,
                  e_s[0][mt][0], e_s[0][mt][1], e_s[0][mt][2], e_s[0][mt][3]);
        unsigned bh1 = bp[8];
#pragma unroll
        for (int mt = 0; mt < 2; mt++)
            MMA_Z(e_s[1][mt][0], e_s[1][mt][1], e_s[1][mt][2], e_s[1][mt][3],
                  Ah0[mt], Ah1[mt], Al0[mt], Al1[mt], bh1, bh1);
    }

    // ---- main loop: nt = 0..62 ----
#pragma unroll 2
    for (int nt = 0; nt < NTILE - 1; nt++) {
        int sc = nt & 1;        // slot of tile nt (and of tile nt+2)
        int sn = sc ^ 1;        // slot of tile nt+1

        // d(nt+1) = A*B_lo(nt+1) + e(nt+1)
        unsigned bl = bp[OFF_RLO + (nt + 1) * 8];
#pragma unroll
        for (int mt = 0; mt < 2; mt++)
            MMA_C(d_s[sn][mt][0], d_s[sn][mt][1], d_s[sn][mt][2], d_s[sn][mt][3],
                  Ah0[mt], Ah1[mt], Al0[mt], Al1[mt], bl, bz,
                  e_s[sn][mt][0], e_s[sn][mt][1], e_s[sn][mt][2], e_s[sn][mt][3]);

        // e(nt+2) = A*B_hi(nt+2)   (nt=62 reads pad word 512 < SW: harmless)
        unsigned bh = bp[(nt + 2) * 8];
#pragma unroll
        for (int mt = 0; mt < 2; mt++)
            MMA_Z(e_s[sc][mt][0], e_s[sc][mt][1], e_s[sc][mt][2], e_s[sc][mt][3],
                  Ah0[mt], Ah1[mt], Al0[mt], Al1[mt], bh, bh);

        // mins on d(nt) -- produced one full iteration ago
#pragma unroll
        for (int mt = 0; mt < 2; mt++) {
            mnA[mt] = fminf(mnA[mt], fminf(d_s[sc][mt][0], d_s[sc][mt][1]));
            mnB[mt] = fminf(mnB[mt], fminf(d_s[sc][mt][2], d_s[sc][mt][3]));
        }
    }
    // drain: mins on d(63) (slot 63&1 = 1)
#pragma unroll
    for (int mt = 0; mt < 2; mt++) {
        mnA[mt] = fminf(mnA[mt], fminf(d_s[1][mt][0], d_s[1][mt][1]));
        mnB[mt] = fminf(mnB[mt], fminf(d_s[1][mt][2], d_s[1][mt][3]));
    }

    // ---- epilogue: quad-min over cols, sqrt, sum ----
    float acc = 0.0f;
#pragma unroll
    for (int mt = 0; mt < 2; mt++) {
        float m0 = mnA[mt], m1 = mnB[mt];
#pragma unroll
        for (int off = 1; off <= 2; off <<= 1) {
            m0 = fminf(m0, __shfl_xor_sync(0xFFFFFFFFu, m0, off));
            m1 = fminf(m1, __shfl_xor_sync(0xFFFFFFFFu, m1, off));
        }
        if (lk == 0) {
            int r = mbase + mt * 16 + lq;
            acc += sqrtf(fmaxf(pn_s[r] + m0, 0.0f));
            acc += sqrtf(fmaxf(pn_s[r + 8] + m1, 0.0f));
        }
    }
    red[tid] = acc;
    __syncthreads();

#pragma unroll
    for (int s = NT / 2; s >= 32; s >>= 1) {   // fold down to 32 inclusive
        if (tid < s) red[tid] += red[tid + s];
        __syncthreads();
    }
    if (tid < 32) {
        float v = red[tid];
#pragma unroll
        for (int o = 16; o > 0; o >>= 1)
            v += __shfl_down_sync(0xFFFFFFFFu, v, o);
        if (tid == 0) {
            float add = v * (1.0f / NP);
            float sc  = pred_s[b * HW + pix];
            g_part[blk] = (add * sc - SCORING_WEIGHT * logf(sc)) * (1.0f / NBLK);
            __threadfence();
            unsigned old = atomicAdd(&g_count, 1u);
            s_last = (old == NBLK - 1);
        }
    }
    __syncthreads();

    // ---- last CTA: reduce 408 partials + inf/nan guard ----
    if (s_last && tid < 32) {
        __threadfence();
        float v = 0.0f;
        for (int i = tid; i < NBLK; i += 32) v += __ldcg(&g_part[i]);
#pragma unroll
        for (int o = 16; o > 0; o >>= 1)
            v += __shfl_down_sync(0xFFFFFFFFu, v, o);
        if (tid == 0) {
            if (isinf(v) || isnan(v)) v = 0.0f;
            out[0] = v;
            g_count = 0;   // reset for next launch / graph replay
        }
    }
}

// ---------------------------------------------------------------------------
// Inputs (metadata order): pred_r, pred_t, pred_s, mask, gt_r, gt_t,
//                          model_xyz, cls_ids
// ---------------------------------------------------------------------------
extern "C" void kernel_launch(void* const* d_in, const int* in_sizes, int n_in,
                              void* d_out, int out_size)
{
    const float* pred_r = (const float*)d_in[0];
    const float* pred_t = (const float*)d_in[1];
    const float* pred_s = (const float*)d_in[2];
    // d_in[3] = mask (unused)
    const float* gt_r   = (const float*)d_in[4];
    const float* gt_t   = (const float*)d_in[5];
    const float* model  = (const float*)d_in[6];
    // d_in[7] = cls_ids (unused)

    fused_kernel<<<NBLK, NT, SMEM_WORDS * 4>>>(pred_r, pred_t, pred_s,
                                               gt_r, gt_t, model,
                                               (float*)d_out);
}

// round 17
// speedup vs baseline: 1.2221x; 1.2221x over previous
#include <cuda_runtime.h>
#include <math.h>

#define BS   8
#define HW   1024
#define STEP 20
#define NS   51            // hw // STEP
#define NP   512           // model points
#define NBLK (BS * NS)     // 408 hypotheses
#define NT   256           // 8 warps, 4 m-tiles (64 query rows) each
#define NTILE 64           // n-tiles of 8 GT points
#define SW   536           // smem plane stride (words): 512 + pad
#define SCORING_WEIGHT 0.01f

// smem (words): [planes 8*SW][pn_s NP][red NT]
#define OFF_PN  (8 * SW)
#define OFF_RED (8 * SW + NP)
#define SMEM_WORDS (8 * SW + NP + NT)

// Scratch (no allocations allowed)
__device__ float    g_part[NBLK];
__device__ unsigned g_count = 0;   // last-block-done counter; self-resetting

__device__ __forceinline__ unsigned f2tf(float f) {
    unsigned r; asm("cvt.rna.tf32.f32 %0, %1;" : "=r"(r) : "f"(f)); return r;
}

// D = A(tf32 m16k8,row) * B(tf32 k8n8,col) + 0.
// A cols 4..7 duplicate cols 0..3, so fragment regs a2=a0, a3=a1.
#define MMA1(D0,D1,D2,D3,A0,A1,B0,B1)                                          \
    asm("mma.sync.aligned.m16n8k8.row.col.f32.tf32.tf32.f32 "                  \
        "{%0,%1,%2,%3}, {%4,%5,%4,%5}, {%6,%7}, {%8,%8,%8,%8};"                \
        : "=f"(D0),"=f"(D1),"=f"(D2),"=f"(D3)                                  \
        : "r"(A0),"r"(A1), "r"(B0),"r"(B1), "f"(0.0f))

// ---------------------------------------------------------------------------
// One block per hypothesis, 8 warps, 4 m-tiles (64 query rows) per warp.
// SINGLE-HMMA split-precision NN:
//   A (m16 x k8) = [tf32(-2p) k0..2 | 1 | tf32(-2p) k4..6 | 1]
//   B (k8 x n8)  = [g_hi k0..2 | gn_hi | g_lo k4..6 | gn_lo]
//     with g_lo = tf32(g - g_hi), gn_hi + gn_lo = gn (split exact-ish)
//   D = tf32(-2p) . g  +  gn     (full B precision; only A-lo dropped)
// One HMMA per (m-tile, n-tile); all HMMAs independent; min deferred one
// iteration. Single wave: 408 CTAs <= 148 SMs x occ 4.
// ---------------------------------------------------------------------------
__global__ __launch_bounds__(NT, 4) void fused_kernel(
    const float* __restrict__ pred_r,
    const float* __restrict__ pred_t,
    const float* __restrict__ pred_s,
    const float* __restrict__ gt_r,
    const float* __restrict__ gt_t,
    const float* __restrict__ model,
    float* __restrict__ out)
{
    extern __shared__ unsigned dsm[];
    float* pn_s = (float*)(dsm + OFF_PN);
    float* red  = (float*)(dsm + OFF_RED);
    __shared__ bool s_last;

    int blk = blockIdx.x;
    int b   = blk / NS;
    int pix = (blk % NS) * STEP;
    int tid = threadIdx.x;

    const float* m = model + b * 3 * NP;

    // ---- pose (redundant per thread) ----
    const float* pr = pred_r + b * 4 * HW + pix;
    float q0 = pr[0], q1 = pr[HW], q2 = pr[2 * HW], q3 = pr[3 * HW];
    float inv = rsqrtf(q0 * q0 + q1 * q1 + q2 * q2 + q3 * q3);
    q0 *= inv; q1 *= inv; q2 *= inv; q3 *= inv;

    float R00 = 1.0f - 2.0f * (q2 * q2 + q3 * q3);
    float R01 = 2.0f * (q1 * q2 - q0 * q3);
    float R02 = 2.0f * (q0 * q2 + q1 * q3);
    float R10 = 2.0f * (q1 * q2 + q3 * q0);
    float R11 = 1.0f - 2.0f * (q1 * q1 + q3 * q3);
    float R12 = 2.0f * (q2 * q3 - q0 * q1);
    float R20 = 2.0f * (q1 * q3 - q0 * q2);
    float R21 = 2.0f * (q0 * q1 + q2 * q3);
    float R22 = 1.0f - 2.0f * (q1 * q1 + q2 * q2);

    const float* pt = pred_t + b * 3 * HW + pix;
    float tx = pt[0], ty = pt[HW], tz = pt[2 * HW];

    const float* GR = gt_r + b * 9;
    const float* GTt = gt_t + b * 3;
    float G0 = GR[0], G1 = GR[1], G2 = GR[2];
    float G3 = GR[3], G4 = GR[4], G5 = GR[5];
    float G6 = GR[6], G7 = GR[7], G8 = GR[8];
    float T0 = GTt[0], T1 = GTt[1], T2 = GTt[2];

    // ---- phase 1: 2 model points/thread: pred -> A staging, gt kept ----
    float gv[2][4];
#pragma unroll
    for (int k = 0; k < 2; k++) {
        int p = tid + k * NT;
        float vx = m[p], vy = m[NP + p], vz = m[2 * NP + p];

        float px = fmaf(R00, vx, fmaf(R01, vy, fmaf(R02, vz, tx)));
        float py = fmaf(R10, vx, fmaf(R11, vy, fmaf(R12, vz, ty)));
        float pz = fmaf(R20, vx, fmaf(R21, vy, fmaf(R22, vz, tz)));
        pn_s[p] = fmaf(px, px, fmaf(py, py, pz * pz));
        dsm[0 * SW + p] = f2tf(-2.0f * px);
        dsm[1 * SW + p] = f2tf(-2.0f * py);
        dsm[2 * SW + p] = f2tf(-2.0f * pz);
        dsm[3 * SW + p] = f2tf(1.0f);

        float gx = fmaf(G0, vx, fmaf(G1, vy, fmaf(G2, vz, T0)));
        float gy = fmaf(G3, vx, fmaf(G4, vy, fmaf(G5, vz, T1)));
        float gz = fmaf(G6, vx, fmaf(G7, vy, fmaf(G8, vz, T2)));
        gv[k][0] = gx; gv[k][1] = gy; gv[k][2] = gz;
        gv[k][3] = fmaf(gx, gx, fmaf(gy, gy, gz * gz));
    }
    __syncthreads();

    int lane = tid & 31;
    int w    = tid >> 5;        // warp 0..7
    int lq   = lane >> 2;       // 0..7
    int lk   = lane & 3;        // 0..3
    int mbase = w * 64;

    // ---- phase 2: A fragments for 4 m-tiles (2 regs each, cols dup) ----
    unsigned a0[4], a1[4];
#pragma unroll
    for (int mt = 0; mt < 4; mt++) {
        int r0 = mbase + mt * 16 + lq;
        a0[mt] = dsm[lk * SW + r0];
        a1[mt] = dsm[lk * SW + r0 + 8];
    }
    __syncthreads();

    // ---- phase 3: GT -> B planes (overwrite A staging) ----
#pragma unroll
    for (int k = 0; k < 2; k++) {
        int p = tid + k * NT;
#pragma unroll
        for (int c = 0; c < 3; c++) {
            unsigned hi = f2tf(gv[k][c]);
            dsm[c * SW + p]       = hi;                                  // g_hi
            dsm[(4 + c) * SW + p] = f2tf(gv[k][c] - __uint_as_float(hi)); // g_lo
        }
        unsigned gnh = f2tf(gv[k][3]);
        dsm[3 * SW + p] = gnh;                                           // gn_hi
        dsm[7 * SW + p] = f2tf(gv[k][3] - __uint_as_float(gnh));         // gn_lo
    }
    __syncthreads();

    float mnA[4], mnB[4];
#pragma unroll
    for (int mt = 0; mt < 4; mt++) { mnA[mt] = 3.0e38f; mnB[mt] = 3.0e38f; }

    const unsigned* bp0 = dsm + lk * SW + lq;         // B row k = lk
    const unsigned* bp1 = dsm + (lk + 4) * SW + lq;   // B row k = lk+4

    // ---- pipeline prologue: d(0), prefetch b(1) ----
    float d[2][4][4];
    {
        unsigned b0 = bp0[0], b1 = bp1[0];
#pragma unroll
        for (int mt = 0; mt < 4; mt++)
            MMA1(d[0][mt][0], d[0][mt][1], d[0][mt][2], d[0][mt][3],
                 a0[mt], a1[mt], b0, b1);
    }
    unsigned b0n = bp0[8], b1n = bp1[8];

    // ---- main loop: issue d(nt+1), prefetch b(nt+2), min d(nt) ----
#pragma unroll 2
    for (int nt = 0; nt < NTILE - 1; nt++) {
        int sc = nt & 1, sn = sc ^ 1;
#pragma unroll
        for (int mt = 0; mt < 4; mt++)
            MMA1(d[sn][mt][0], d[sn][mt][1], d[sn][mt][2], d[sn][mt][3],
                 a0[mt], a1[mt], b0n, b1n);
        b0n = bp0[(nt + 2) * 8];   // nt=62 reads pad word 512 < SW: harmless
        b1n = bp1[(nt + 2) * 8];
#pragma unroll
        for (int mt = 0; mt < 4; mt++) {
            mnA[mt] = fminf(mnA[mt], fminf(d[sc][mt][0], d[sc][mt][1]));
            mnB[mt] = fminf(mnB[mt], fminf(d[sc][mt][2], d[sc][mt][3]));
        }
    }
    // drain d(63) (slot 63&1 = 1)
#pragma unroll
    for (int mt = 0; mt < 4; mt++) {
        mnA[mt] = fminf(mnA[mt], fminf(d[1][mt][0], d[1][mt][1]));
        mnB[mt] = fminf(mnB[mt], fminf(d[1][mt][2], d[1][mt][3]));
    }

    // ---- epilogue: min over columns (lanes lk), sqrt, sum ----
    float acc = 0.0f;
#pragma unroll
    for (int mt = 0; mt < 4; mt++) {
        float m0 = mnA[mt], m1 = mnB[mt];
#pragma unroll
        for (int off = 1; off <= 2; off <<= 1) {
            m0 = fminf(m0, __shfl_xor_sync(0xFFFFFFFFu, m0, off));
            m1 = fminf(m1, __shfl_xor_sync(0xFFFFFFFFu, m1, off));
        }
        if (lk == 0) {
            int r = mbase + mt * 16 + lq;
            acc += sqrtf(fmaxf(pn_s[r] + m0, 0.0f));
            acc += sqrtf(fmaxf(pn_s[r + 8] + m1, 0.0f));
        }
    }
    red[tid] = acc;
    __syncthreads();

#pragma unroll
    for (int s = NT / 2; s >= 32; s >>= 1) {   // fold down to 32 inclusive
        if (tid < s) red[tid] += red[tid + s];
        __syncthreads();
    }
    if (tid < 32) {
        float v = red[tid];
#pragma unroll
        for (int o = 16; o > 0; o >>= 1)
            v += __shfl_down_sync(0xFFFFFFFFu, v, o);
        if (tid == 0) {
            float add = v * (1.0f / NP);
            float sc  = pred_s[b * HW + pix];
            g_part[blk] = (add * sc - SCORING_WEIGHT * logf(sc)) * (1.0f / NBLK);
            __threadfence();
            unsigned old = atomicAdd(&g_count, 1u);
            s_last = (old == NBLK - 1);
        }
    }
    __syncthreads();

    // ---- last CTA: reduce 408 partials + inf/nan guard ----
    if (s_last && tid < 32) {
        __threadfence();
        float v = 0.0f;
        for (int i = tid; i < NBLK; i += 32) v += __ldcg(&g_part[i]);
#pragma unroll
        for (int o = 16; o > 0; o >>= 1)
            v += __shfl_down_sync(0xFFFFFFFFu, v, o);
        if (tid == 0) {
            if (isinf(v) || isnan(v)) v = 0.0f;
            out[0] = v;
            g_count = 0;   // reset for next launch / graph replay
        }
    }
}

// ---------------------------------------------------------------------------
// Inputs (metadata order): pred_r, pred_t, pred_s, mask, gt_r, gt_t,
//                          model_xyz, cls_ids
// ---------------------------------------------------------------------------
extern "C" void kernel_launch(void* const* d_in, const int* in_sizes, int n_in,
                              void* d_out, int out_size)
{
    const float* pred_r = (const float*)d_in[0];
    const float* pred_t = (const float*)d_in[1];
    const float* pred_s = (const float*)d_in[2];
    // d_in[3] = mask (unused)
    const float* gt_r   = (const float*)d_in[4];
    const float* gt_t   = (const float*)d_in[5];
    const float* model  = (const float*)d_in[6];
    // d_in[7] = cls_ids (unused)

    fused_kernel<<<NBLK, NT, SMEM_WORDS * 4>>>(pred_r, pred_t, pred_s,
                                               gt_r, gt_t, model,
                                               (float*)d_out);
}